// round 15
// baseline (speedup 1.0000x reference)
#include <cuda_runtime.h>
#include <cuda_fp16.h>
#include <cstdint>

#define BB 8
#define SS 2048
#define DD 512
#define UU 512
#define QT2 64
#define NT2 (SS/QT2)
#define WIN2 320
#define SCALE 0.044194173824159216f

// ---------------------------------------------------------------------------
// Scratch (fp16)
// ---------------------------------------------------------------------------
__device__ __half g_xh[(size_t)BB * SS * DD];
__device__ __half g_wth[3ull * UU * DD];           // W transposed [w][n][k]
__device__ __half g_q[(size_t)BB * SS * UU];
__device__ __half g_k[(size_t)BB * SS * UU];
__device__ __half g_v[(size_t)BB * SS * UU];

// ---------------------------------------------------------------------------
// Helpers (baseline PTX only — valid under compute_103)
// ---------------------------------------------------------------------------
__device__ __forceinline__ uint32_t smem_u32(const void* p) {
    uint32_t a;
    asm("{ .reg .u64 t; cvta.to.shared.u64 t, %1; cvt.u32.u64 %0, t; }"
        : "=r"(a) : "l"(p));
    return a;
}
#define SWZ(o) ((o) ^ (((o) >> 3) & 0x70))

__device__ __forceinline__ void cp16(uint32_t s, const void* g) {
    asm volatile("cp.async.cg.shared.global [%0], [%1], 16;" :: "r"(s), "l"(g));
}
#define CP_COMMIT() asm volatile("cp.async.commit_group;" ::: "memory")
#define CP_WAIT(n)  asm volatile("cp.async.wait_group %0;" :: "n"(n) : "memory")

__device__ __forceinline__ void ldm_x4(uint32_t* r, uint32_t a) {
    asm volatile("ldmatrix.sync.aligned.m8n8.x4.shared.b16 {%0,%1,%2,%3}, [%4];"
        : "=r"(r[0]), "=r"(r[1]), "=r"(r[2]), "=r"(r[3]) : "r"(a));
}
__device__ __forceinline__ void ldm_x4t(uint32_t* r, uint32_t a) {
    asm volatile("ldmatrix.sync.aligned.m8n8.x4.trans.shared.b16 {%0,%1,%2,%3}, [%4];"
        : "=r"(r[0]), "=r"(r[1]), "=r"(r[2]), "=r"(r[3]) : "r"(a));
}
__device__ __forceinline__ void mma_f16(float* d, const uint32_t* a, const uint32_t* b) {
    asm volatile("mma.sync.aligned.m16n8k16.row.col.f32.f16.f16.f32 "
        "{%0,%1,%2,%3}, {%4,%5,%6,%7}, {%8,%9}, {%0,%1,%2,%3};"
        : "+f"(d[0]), "+f"(d[1]), "+f"(d[2]), "+f"(d[3])
        : "r"(a[0]), "r"(a[1]), "r"(a[2]), "r"(a[3]), "r"(b[0]), "r"(b[1]));
}
__device__ __forceinline__ int iclamp(int v, int lo, int hi) {
    return v < lo ? lo : (v > hi ? hi : v);
}

// ---------------------------------------------------------------------------
// Prep (merged): y==0 grid converts x; y==1 grid transposes+converts W.
// ---------------------------------------------------------------------------
__global__ __launch_bounds__(256) void prep_all(
    const float* __restrict__ x,
    const float* __restrict__ Wq, const float* __restrict__ Wk, const float* __restrict__ Wv)
{
    if (blockIdx.y == 0) {
        // x: fp32 -> fp16, 8192 blocks of 256 threads x float4
        const size_t i4 = (size_t)blockIdx.x * 256 + threadIdx.x;
        float4 v = ((const float4*)x)[i4];
        __half2* oh = (__half2*)g_xh;
        oh[i4 * 2]     = __half2(__float2half_rn(v.x), __float2half_rn(v.y));
        oh[i4 * 2 + 1] = __half2(__float2half_rn(v.z), __float2half_rn(v.w));
    } else {
        // W transpose: blockIdx.x encodes (n0, k0, w): 16 x 16 x 3 = 768 blocks
        __shared__ float t[32][33];
        const int bid = blockIdx.x;
        const int w  = bid / 256;
        const int r2 = bid % 256;
        const int n0 = (r2 & 15) * 32;
        const int k0 = (r2 >> 4) * 32;
        const float* __restrict__ W = (w == 0) ? Wq : (w == 1) ? Wk : Wv;
        const int tx = threadIdx.x & 31;
        const int ty = threadIdx.x >> 5;
#pragma unroll
        for (int i = 0; i < 4; i++) {
            const int r = ty + i * 8;
            t[r][tx] = W[(size_t)(k0 + r) * UU + n0 + tx];
        }
        __syncthreads();
        const size_t base = (size_t)w * UU * DD;
#pragma unroll
        for (int i = 0; i < 4; i++) {
            const int r = ty + i * 8;
            g_wth[base + (size_t)(n0 + r) * DD + k0 + tx] = __float2half_rn(t[tx][r]);
        }
    }
}

// ---------------------------------------------------------------------------
// QKV GEMM: 1-pass fp16, CTA 128x128, 8 warps 32x64, 3-stage cp.async,
// 2 CTAs/SM. grid (4, 128, 3), 256 thr, 96 KB smem.
// ---------------------------------------------------------------------------
#define Q_A 0
#define Q_B 16384
#define Q_BUF 32768
#define GEMM_SMEM (3 * Q_BUF)

__global__ __launch_bounds__(256, 2) void qkv_tc(
    const float* __restrict__ bq, const float* __restrict__ bk, const float* __restrict__ bv)
{
    extern __shared__ char sm[];
    const uint32_t sbase = smem_u32(sm);
    const int tid  = threadIdx.x;
    const int warp = tid >> 5;
    const int lane = tid & 31;
    const int w3 = blockIdx.z;
    const int n0 = blockIdx.x * 128;
    const int m0 = blockIdx.y * 128;

    const int wm = (warp & 3) * 32;
    const int wn = (warp >> 2) * 64;

    const __half* __restrict__ xh = g_xh + (size_t)m0 * DD;
    const __half* __restrict__ wh = g_wth + (size_t)w3 * UU * DD + (size_t)n0 * DD;

    auto issue_chunk = [&](int c) {
        const int kc0 = c * 64;
        const uint32_t bs = sbase + (c % 3) * Q_BUF;
#pragma unroll
        for (int i = 0; i < 4; i++) {
            const int f = tid + i * 256;
            const int row = f >> 3, seg = (f & 7) * 16;
            const uint32_t so = SWZ(row * 128 + seg);
            cp16(bs + Q_A + so, (const char*)(xh + (size_t)row * DD + kc0) + seg);
            cp16(bs + Q_B + so, (const char*)(wh + (size_t)row * DD + kc0) + seg);
        }
        CP_COMMIT();
    };

    float acc[2][8][4];
#pragma unroll
    for (int mt = 0; mt < 2; mt++)
#pragma unroll
        for (int nt = 0; nt < 8; nt++)
#pragma unroll
            for (int i = 0; i < 4; i++) acc[mt][nt][i] = 0.f;

    issue_chunk(0);
    issue_chunk(1);

    const int lsub = lane >> 3;
    const int lrow = lane & 7;
    const int a_ro = (lsub & 1) * 8;
    const int a_ko = (lsub >> 1) * 16;
    const int b_ro = (lsub >> 1) * 8;
    const int b_ko = (lsub & 1) * 16;

    for (int c = 0; c < 8; c++) {
        if (c < 6)       { issue_chunk(c + 2); CP_WAIT(2); }
        else if (c == 6) { CP_WAIT(1); }
        else             { CP_WAIT(0); }
        __syncthreads();

        const uint32_t bs = sbase + (c % 3) * Q_BUF;

#pragma unroll
        for (int ks = 0; ks < 4; ks++) {
            const int kb = ks * 32;
            uint32_t ah[2][4];
#pragma unroll
            for (int mt = 0; mt < 2; mt++) {
                const uint32_t off = SWZ((wm + mt * 16 + lrow + a_ro) * 128 + kb + a_ko);
                ldm_x4(ah[mt], bs + Q_A + off);
            }
#pragma unroll
            for (int ntp = 0; ntp < 4; ntp++) {
                const uint32_t off = SWZ((wn + ntp * 16 + b_ro + lrow) * 128 + kb + b_ko);
                uint32_t bh[4];
                ldm_x4(bh, bs + Q_B + off);
#pragma unroll
                for (int t = 0; t < 2; t++)
#pragma unroll
                    for (int mt = 0; mt < 2; mt++)
                        mma_f16(acc[mt][ntp * 2 + t], ah[mt], bh + t * 2);
            }
        }
        __syncthreads();
    }

    const float* __restrict__ bias = (w3 == 0) ? bq : (w3 == 1) ? bk : bv;
    __half* __restrict__ oh = (w3 == 0) ? g_q : (w3 == 1) ? g_k : g_v;
    const int grp = lane >> 2;
    const int qd  = lane & 3;
#pragma unroll
    for (int nt = 0; nt < 8; nt++) {
        const int col = n0 + wn + nt * 8 + qd * 2;
        const float b0 = bias[col], b1 = bias[col + 1];
#pragma unroll
        for (int mt = 0; mt < 2; mt++) {
            const int r0 = m0 + wm + mt * 16 + grp;
            *(__half2*)&oh[(size_t)r0 * UU + col] = __half2(
                __float2half_rn(acc[mt][nt][0] + b0),
                __float2half_rn(acc[mt][nt][1] + b1));
            *(__half2*)&oh[(size_t)(r0 + 8) * UU + col] = __half2(
                __float2half_rn(acc[mt][nt][2] + b0),
                __float2half_rn(acc[mt][nt][3] + b1));
        }
    }
}

// ---------------------------------------------------------------------------
// Fused attention (unchanged R14): phase 1 + register softmax (no max pass),
// normalization folded into phase-2 epilogue. Phase 2 kc-outer, full 512-d.
// ---------------------------------------------------------------------------
#define FA_A 0
#define FA_B 8192
#define FA_BUF 49152
#define P_OFF 0
#define V_OFF 49152
#define RED_OFF (V_OFF + 2 * 65536)
#define FA_SMEM (RED_OFF + 2048)

__global__ __launch_bounds__(256, 1) void attn_fused(float* __restrict__ out)
{
    extern __shared__ char sm[];
    const uint32_t sbase = smem_u32(sm);
    const int tid  = threadIdx.x;
    const int warp = tid >> 5;
    const int lane = tid & 31;
    const int b  = blockIdx.y;
    const int q0 = blockIdx.x * QT2;
    const int kstart = q0 - 128;

    const __half* __restrict__ qp = g_q + (size_t)(b * SS + q0) * UU;
    const __half* __restrict__ kp = g_k + (size_t)b * SS * UU;
    const __half* __restrict__ vp = g_v + (size_t)b * SS * UU;

    const int lsub = lane >> 3;
    const int lrow = lane & 7;
    const int a_ro = (lsub & 1) * 8;
    const int a_ko = (lsub >> 1) * 16;
    const int b_ro = (lsub >> 1) * 8;
    const int b_ko = (lsub & 1) * 16;

    auto issueK = [&](int c, int buf) {
        const int kc0 = c * 64;
        const uint32_t bs = sbase + buf * FA_BUF;
#pragma unroll
        for (int i = 0; i < 2; i++) {
            const int f = tid + i * 256;
            const int row = f >> 3, seg = (f & 7) * 16;
            const uint32_t so = SWZ(row * 128 + seg);
            cp16(bs + FA_A + so, (const char*)(qp + (size_t)row * UU + kc0) + seg);
        }
#pragma unroll
        for (int i = 0; i < 10; i++) {
            const int f = tid + i * 256;
            const int row = f >> 3, seg = (f & 7) * 16;
            const int j = iclamp(kstart + row, 0, SS - 1);
            const uint32_t so = SWZ(row * 128 + seg);
            cp16(bs + FA_B + so, (const char*)(kp + (size_t)j * UU + kc0) + seg);
        }
        CP_COMMIT();
    };

    float acc[2][10][4];
#pragma unroll
    for (int mt = 0; mt < 2; mt++)
#pragma unroll
        for (int nt = 0; nt < 10; nt++)
#pragma unroll
            for (int i = 0; i < 4; i++) acc[mt][nt][i] = 0.f;

    issueK(0, 0);

    const int wm = (warp & 1) * 32;
    const int wng = warp >> 1;
    const int wn = wng * 80;

    for (int c = 0; c < 8; c++) {
        if (c < 7) { issueK(c + 1, (c + 1) & 1); CP_WAIT(1); }
        else       { CP_WAIT(0); }
        __syncthreads();

        const uint32_t bs = sbase + (c & 1) * FA_BUF;
#pragma unroll
        for (int ks = 0; ks < 4; ks++) {
            const int kb = ks * 32;
            uint32_t ah[2][4];
#pragma unroll
            for (int mt = 0; mt < 2; mt++) {
                const uint32_t off = SWZ((wm + mt * 16 + lrow + a_ro) * 128 + kb + a_ko);
                ldm_x4(ah[mt], bs + FA_A + off);
            }
#pragma unroll
            for (int ntp = 0; ntp < 5; ntp++) {
                const uint32_t off = SWZ((wn + ntp * 16 + b_ro + lrow) * 128 + kb + b_ko);
                uint32_t bh[4];
                ldm_x4(bh, bs + FA_B + off);
#pragma unroll
                for (int t = 0; t < 2; t++)
#pragma unroll
                    for (int mt = 0; mt < 2; mt++)
                        mma_f16(acc[mt][ntp * 2 + t], ah[mt], bh + t * 2);
            }
        }
        __syncthreads();
    }

    auto issueV = [&](int kc, int vbuf) {
        const uint32_t bs = sbase + V_OFF + vbuf * 65536;
#pragma unroll
        for (int i = 0; i < 16; i++) {
            const int f = tid + i * 256;
            const int sub = f >> 9;
            const int row = (f >> 3) & 63;
            const int seg = (f & 7) * 16;
            const int j = iclamp(kstart + kc * 64 + row, 0, SS - 1);
            const uint32_t so = SWZ(row * 128 + seg);
            cp16(bs + sub * 8192 + so,
                 (const char*)(vp + (size_t)j * UU + sub * 64) + seg);
        }
        CP_COMMIT();
    };
    issueV(0, 0);

    // Register softmax (no max pass)
    const int grp = lane >> 2;
    const int qd  = lane & 3;
    const int chi = SS - 1 - kstart;

    float* redsum = (float*)(sm + RED_OFF);

    int cminA[2], cmaxA[2], cminB[2], cmaxB[2];
    int rowA[2], rowB[2];
#pragma unroll
    for (int mt = 0; mt < 2; mt++) {
        rowA[mt] = wm + mt * 16 + grp;
        rowB[mt] = rowA[mt] + 8;
        cminA[mt] = (rowA[mt] > -kstart) ? rowA[mt] : -kstart;
        cmaxA[mt] = (rowA[mt] + 256 < chi) ? rowA[mt] + 256 : chi;
        cminB[mt] = (rowB[mt] > -kstart) ? rowB[mt] : -kstart;
        cmaxB[mt] = (rowB[mt] + 256 < chi) ? rowB[mt] + 256 : chi;
    }

    float sA[2] = {0.f, 0.f}, sB[2] = {0.f, 0.f};
#pragma unroll
    for (int mt = 0; mt < 2; mt++) {
#pragma unroll
        for (int nt = 0; nt < 10; nt++) {
            const int c0 = wn + nt * 8 + qd * 2;
            const int c1 = c0 + 1;
            float e;
            e = (c0 >= cminA[mt] && c0 <= cmaxA[mt]) ? __expf(acc[mt][nt][0] * SCALE) : 0.f;
            acc[mt][nt][0] = e; sA[mt] += e;
            e = (c1 >= cminA[mt] && c1 <= cmaxA[mt]) ? __expf(acc[mt][nt][1] * SCALE) : 0.f;
            acc[mt][nt][1] = e; sA[mt] += e;
            e = (c0 >= cminB[mt] && c0 <= cmaxB[mt]) ? __expf(acc[mt][nt][2] * SCALE) : 0.f;
            acc[mt][nt][2] = e; sB[mt] += e;
            e = (c1 >= cminB[mt] && c1 <= cmaxB[mt]) ? __expf(acc[mt][nt][3] * SCALE) : 0.f;
            acc[mt][nt][3] = e; sB[mt] += e;
        }
    }
#pragma unroll
    for (int off = 1; off <= 2; off <<= 1) {
#pragma unroll
        for (int mt = 0; mt < 2; mt++) {
            sA[mt] += __shfl_xor_sync(0xFFFFFFFFu, sA[mt], off);
            sB[mt] += __shfl_xor_sync(0xFFFFFFFFu, sB[mt], off);
        }
    }
    if (qd == 0) {
#pragma unroll
        for (int mt = 0; mt < 2; mt++) {
            redsum[wng * 64 + rowA[mt]] = sA[mt];
            redsum[wng * 64 + rowB[mt]] = sB[mt];
        }
    }

    // store unnormalized P (fp16)
#pragma unroll
    for (int mt = 0; mt < 2; mt++) {
#pragma unroll
        for (int nt = 0; nt < 10; nt++) {
            const int c0 = wn + nt * 8 + qd * 2;
            const uint32_t base0 = P_OFF + (c0 >> 6) * 8192;
            const uint32_t oA = base0 + SWZ(rowA[mt] * 128 + (c0 & 63) * 2);
            const uint32_t oB = base0 + SWZ(rowB[mt] * 128 + (c0 & 63) * 2);
            *(__half2*)(sm + oA) = __half2(__float2half_rn(acc[mt][nt][0]),
                                           __float2half_rn(acc[mt][nt][1]));
            *(__half2*)(sm + oB) = __half2(__float2half_rn(acc[mt][nt][2]),
                                           __float2half_rn(acc[mt][nt][3]));
        }
    }
    __syncthreads();

    float invA[2], invB[2];
#pragma unroll
    for (int mt = 0; mt < 2; mt++) {
        invA[mt] = 1.0f / (redsum[rowA[mt]] + redsum[64 + rowA[mt]]
                         + redsum[128 + rowA[mt]] + redsum[192 + rowA[mt]]);
        invB[mt] = 1.0f / (redsum[rowB[mt]] + redsum[64 + rowB[mt]]
                         + redsum[128 + rowB[mt]] + redsum[192 + rowB[mt]]);
    }

    // Phase 2: out = P V (kc outer, full 512 d)
    const int wd = wng * 128;
    const int sb = wd >> 6;

    float acc2[2][16][4];
#pragma unroll
    for (int mt = 0; mt < 2; mt++)
#pragma unroll
        for (int nt = 0; nt < 16; nt++)
#pragma unroll
            for (int i = 0; i < 4; i++) acc2[mt][nt][i] = 0.f;

    for (int kc = 0; kc < 5; kc++) {
        if (kc < 4) { issueV(kc + 1, (kc + 1) & 1); CP_WAIT(1); }
        else        { CP_WAIT(0); }
        __syncthreads();

        const uint32_t Vb = sbase + V_OFF + (kc & 1) * 65536;
        const uint32_t Ph = sbase + P_OFF + kc * 8192;

#pragma unroll
        for (int ks = 0; ks < 4; ks++) {
            uint32_t ah[2][4];
#pragma unroll
            for (int mt = 0; mt < 2; mt++) {
                const uint32_t off = SWZ((wm + mt * 16 + lrow + a_ro) * 128 + ks * 32 + a_ko);
                ldm_x4(ah[mt], Ph + off);
            }
#pragma unroll
            for (int sub2 = 0; sub2 < 2; sub2++) {
                const uint32_t Vt = Vb + (sb + sub2) * 8192;
#pragma unroll
                for (int ntp = 0; ntp < 4; ntp++) {
                    const uint32_t off = SWZ((ks * 16 + (lsub & 1) * 8 + lrow) * 128
                                             + (ntp * 16 + (lsub >> 1) * 8) * 2);
                    uint32_t bh[4];
                    ldm_x4t(bh, Vt + off);
#pragma unroll
                    for (int t = 0; t < 2; t++)
#pragma unroll
                        for (int mt = 0; mt < 2; mt++)
                            mma_f16(acc2[mt][sub2 * 8 + ntp * 2 + t], ah[mt], bh + t * 2);
                }
            }
        }
        __syncthreads();
    }

#pragma unroll
    for (int mt = 0; mt < 2; mt++) {
        const int r0 = q0 + wm + mt * 16 + grp;
#pragma unroll
        for (int sub2 = 0; sub2 < 2; sub2++) {
#pragma unroll
            for (int ntp = 0; ntp < 4; ntp++) {
#pragma unroll
                for (int t = 0; t < 2; t++) {
                    const int col = wd + sub2 * 64 + ntp * 16 + t * 8 + qd * 2;
                    const int idx = sub2 * 8 + ntp * 2 + t;
                    *(float2*)&out[((size_t)b * SS + r0) * UU + col] =
                        make_float2(acc2[mt][idx][0] * invA[mt], acc2[mt][idx][1] * invA[mt]);
                    *(float2*)&out[((size_t)b * SS + r0 + 8) * UU + col] =
                        make_float2(acc2[mt][idx][2] * invB[mt], acc2[mt][idx][3] * invB[mt]);
                }
            }
        }
    }
}

// ---------------------------------------------------------------------------
extern "C" void kernel_launch(void* const* d_in, const int* in_sizes, int n_in,
                              void* d_out, int out_size)
{
    const float* x  = (const float*)d_in[0];
    const float* Wq = (const float*)d_in[1];
    const float* Wk = (const float*)d_in[2];
    const float* Wv = (const float*)d_in[3];
    const float* bq = (const float*)d_in[4];
    const float* bk = (const float*)d_in[5];
    const float* bv = (const float*)d_in[6];
    float* out = (float*)d_out;

    cudaFuncSetAttribute(qkv_tc,
                         cudaFuncAttributeMaxDynamicSharedMemorySize, GEMM_SMEM);
    cudaFuncSetAttribute(attn_fused,
                         cudaFuncAttributeMaxDynamicSharedMemorySize, FA_SMEM);

    // prep: x-convert blocks (y=0, 8192 blocks) + W-transpose blocks (y=1, 768)
    prep_all<<<dim3(8192, 2), 256>>>(x, Wq, Wk, Wv);
    qkv_tc<<<dim3(UU / 128, BB * SS / 128, 3), 256, GEMM_SMEM>>>(bq, bk, bv);
    attn_fused<<<dim3(NT2, BB), 256, FA_SMEM>>>(out);
}

// round 16
// speedup vs baseline: 1.0502x; 1.0502x over previous
#include <cuda_runtime.h>
#include <cuda_fp16.h>
#include <cstdint>

#define BB 8
#define SS 2048
#define DD 512
#define UU 512
#define QT2 64
#define NT2 (SS/QT2)
#define WIN2 320
#define SCALE 0.044194173824159216f

// ---------------------------------------------------------------------------
// Scratch (fp16)
// ---------------------------------------------------------------------------
__device__ __half g_xh[(size_t)BB * SS * DD];
__device__ __half g_wth[3ull * UU * DD];           // W transposed [w][n][k]
__device__ __half g_q[(size_t)BB * SS * UU];
__device__ __half g_k[(size_t)BB * SS * UU];
__device__ __half g_v[(size_t)BB * SS * UU];

// ---------------------------------------------------------------------------
// Helpers (baseline PTX only — valid under compute_103)
// ---------------------------------------------------------------------------
__device__ __forceinline__ uint32_t smem_u32(const void* p) {
    uint32_t a;
    asm("{ .reg .u64 t; cvta.to.shared.u64 t, %1; cvt.u32.u64 %0, t; }"
        : "=r"(a) : "l"(p));
    return a;
}
#define SWZ(o) ((o) ^ (((o) >> 3) & 0x70))

__device__ __forceinline__ void cp16(uint32_t s, const void* g) {
    asm volatile("cp.async.cg.shared.global [%0], [%1], 16;" :: "r"(s), "l"(g));
}
#define CP_COMMIT() asm volatile("cp.async.commit_group;" ::: "memory")
#define CP_WAIT(n)  asm volatile("cp.async.wait_group %0;" :: "n"(n) : "memory")

__device__ __forceinline__ void ldm_x4(uint32_t* r, uint32_t a) {
    asm volatile("ldmatrix.sync.aligned.m8n8.x4.shared.b16 {%0,%1,%2,%3}, [%4];"
        : "=r"(r[0]), "=r"(r[1]), "=r"(r[2]), "=r"(r[3]) : "r"(a));
}
__device__ __forceinline__ void ldm_x4t(uint32_t* r, uint32_t a) {
    asm volatile("ldmatrix.sync.aligned.m8n8.x4.trans.shared.b16 {%0,%1,%2,%3}, [%4];"
        : "=r"(r[0]), "=r"(r[1]), "=r"(r[2]), "=r"(r[3]) : "r"(a));
}
__device__ __forceinline__ void mma_f16(float* d, const uint32_t* a, const uint32_t* b) {
    asm volatile("mma.sync.aligned.m16n8k16.row.col.f32.f16.f16.f32 "
        "{%0,%1,%2,%3}, {%4,%5,%6,%7}, {%8,%9}, {%0,%1,%2,%3};"
        : "+f"(d[0]), "+f"(d[1]), "+f"(d[2]), "+f"(d[3])
        : "r"(a[0]), "r"(a[1]), "r"(a[2]), "r"(a[3]), "r"(b[0]), "r"(b[1]));
}
__device__ __forceinline__ int iclamp(int v, int lo, int hi) {
    return v < lo ? lo : (v > hi ? hi : v);
}

// ---------------------------------------------------------------------------
// Prep (merged, 1D grid): blocks [0, 8192) convert x; blocks [8192, 8960)
// transpose+convert W (768 blocks: 16 n-tiles x 16 k-tiles x 3 weights).
// ---------------------------------------------------------------------------
__global__ __launch_bounds__(256) void prep_all(
    const float* __restrict__ x,
    const float* __restrict__ Wq, const float* __restrict__ Wk, const float* __restrict__ Wv)
{
    if (blockIdx.x < 8192) {
        const size_t i4 = (size_t)blockIdx.x * 256 + threadIdx.x;
        float4 v = ((const float4*)x)[i4];
        __half2* oh = (__half2*)g_xh;
        oh[i4 * 2]     = __half2(__float2half_rn(v.x), __float2half_rn(v.y));
        oh[i4 * 2 + 1] = __half2(__float2half_rn(v.z), __float2half_rn(v.w));
    } else {
        __shared__ float t[32][33];
        const int bid = blockIdx.x - 8192;      // 0..767
        const int w  = bid / 256;               // 0..2
        const int r2 = bid % 256;
        const int n0 = (r2 & 15) * 32;
        const int k0 = (r2 >> 4) * 32;
        const float* __restrict__ W = (w == 0) ? Wq : (w == 1) ? Wk : Wv;
        const int tx = threadIdx.x & 31;
        const int ty = threadIdx.x >> 5;
#pragma unroll
        for (int i = 0; i < 4; i++) {
            const int r = ty + i * 8;
            t[r][tx] = W[(size_t)(k0 + r) * UU + n0 + tx];
        }
        __syncthreads();
        const size_t base = (size_t)w * UU * DD;
#pragma unroll
        for (int i = 0; i < 4; i++) {
            const int r = ty + i * 8;
            g_wth[base + (size_t)(n0 + r) * DD + k0 + tx] = __float2half_rn(t[tx][r]);
        }
    }
}

// ---------------------------------------------------------------------------
// QKV GEMM: 1-pass fp16 (R14 config). CTA 128x128, 8 warps 32x64,
// 2-stage cp.async, 2 CTAs/SM. grid (4, 128, 3), 256 thr, 64 KB smem.
// ---------------------------------------------------------------------------
#define Q_A 0
#define Q_B 16384
#define Q_BUF 32768
#define GEMM_SMEM (2 * Q_BUF)

__global__ __launch_bounds__(256, 2) void qkv_tc(
    const float* __restrict__ bq, const float* __restrict__ bk, const float* __restrict__ bv)
{
    extern __shared__ char sm[];
    const uint32_t sbase = smem_u32(sm);
    const int tid  = threadIdx.x;
    const int warp = tid >> 5;
    const int lane = tid & 31;
    const int w3 = blockIdx.z;
    const int n0 = blockIdx.x * 128;
    const int m0 = blockIdx.y * 128;

    const int wm = (warp & 3) * 32;
    const int wn = (warp >> 2) * 64;

    const __half* __restrict__ xh = g_xh + (size_t)m0 * DD;
    const __half* __restrict__ wh = g_wth + (size_t)w3 * UU * DD + (size_t)n0 * DD;

    auto issue_chunk = [&](int c, int buf) {
        const int kc0 = c * 64;
        const uint32_t bs = sbase + buf * Q_BUF;
#pragma unroll
        for (int i = 0; i < 4; i++) {
            const int f = tid + i * 256;
            const int row = f >> 3, seg = (f & 7) * 16;
            const uint32_t so = SWZ(row * 128 + seg);
            cp16(bs + Q_A + so, (const char*)(xh + (size_t)row * DD + kc0) + seg);
            cp16(bs + Q_B + so, (const char*)(wh + (size_t)row * DD + kc0) + seg);
        }
        CP_COMMIT();
    };

    float acc[2][8][4];
#pragma unroll
    for (int mt = 0; mt < 2; mt++)
#pragma unroll
        for (int nt = 0; nt < 8; nt++)
#pragma unroll
            for (int i = 0; i < 4; i++) acc[mt][nt][i] = 0.f;

    issue_chunk(0, 0);

    const int lsub = lane >> 3;
    const int lrow = lane & 7;
    const int a_ro = (lsub & 1) * 8;
    const int a_ko = (lsub >> 1) * 16;
    const int b_ro = (lsub >> 1) * 8;
    const int b_ko = (lsub & 1) * 16;

    for (int c = 0; c < 8; c++) {
        if (c < 7) { issue_chunk(c + 1, (c + 1) & 1); CP_WAIT(1); }
        else       { CP_WAIT(0); }
        __syncthreads();

        const uint32_t bs = sbase + (c & 1) * Q_BUF;

#pragma unroll
        for (int ks = 0; ks < 4; ks++) {
            const int kb = ks * 32;
            uint32_t ah[2][4];
#pragma unroll
            for (int mt = 0; mt < 2; mt++) {
                const uint32_t off = SWZ((wm + mt * 16 + lrow + a_ro) * 128 + kb + a_ko);
                ldm_x4(ah[mt], bs + Q_A + off);
            }
#pragma unroll
            for (int ntp = 0; ntp < 4; ntp++) {
                const uint32_t off = SWZ((wn + ntp * 16 + b_ro + lrow) * 128 + kb + b_ko);
                uint32_t bh[4];
                ldm_x4(bh, bs + Q_B + off);
#pragma unroll
                for (int t = 0; t < 2; t++)
#pragma unroll
                    for (int mt = 0; mt < 2; mt++)
                        mma_f16(acc[mt][ntp * 2 + t], ah[mt], bh + t * 2);
            }
        }
        __syncthreads();
    }

    const float* __restrict__ bias = (w3 == 0) ? bq : (w3 == 1) ? bk : bv;
    __half* __restrict__ oh = (w3 == 0) ? g_q : (w3 == 1) ? g_k : g_v;
    const int grp = lane >> 2;
    const int qd  = lane & 3;
#pragma unroll
    for (int nt = 0; nt < 8; nt++) {
        const int col = n0 + wn + nt * 8 + qd * 2;
        const float b0 = bias[col], b1 = bias[col + 1];
#pragma unroll
        for (int mt = 0; mt < 2; mt++) {
            const int r0 = m0 + wm + mt * 16 + grp;
            *(__half2*)&oh[(size_t)r0 * UU + col] = __half2(
                __float2half_rn(acc[mt][nt][0] + b0),
                __float2half_rn(acc[mt][nt][1] + b1));
            *(__half2*)&oh[(size_t)(r0 + 8) * UU + col] = __half2(
                __float2half_rn(acc[mt][nt][2] + b0),
                __float2half_rn(acc[mt][nt][3] + b1));
        }
    }
}

// ---------------------------------------------------------------------------
// Fused attention (unchanged R14): phase 1 + register softmax (no max pass),
// normalization folded into phase-2 epilogue. Phase 2 kc-outer, full 512-d.
// ---------------------------------------------------------------------------
#define FA_A 0
#define FA_B 8192
#define FA_BUF 49152
#define P_OFF 0
#define V_OFF 49152
#define RED_OFF (V_OFF + 2 * 65536)
#define FA_SMEM (RED_OFF + 2048)

__global__ __launch_bounds__(256, 1) void attn_fused(float* __restrict__ out)
{
    extern __shared__ char sm[];
    const uint32_t sbase = smem_u32(sm);
    const int tid  = threadIdx.x;
    const int warp = tid >> 5;
    const int lane = tid & 31;
    const int b  = blockIdx.y;
    const int q0 = blockIdx.x * QT2;
    const int kstart = q0 - 128;

    const __half* __restrict__ qp = g_q + (size_t)(b * SS + q0) * UU;
    const __half* __restrict__ kp = g_k + (size_t)b * SS * UU;
    const __half* __restrict__ vp = g_v + (size_t)b * SS * UU;

    const int lsub = lane >> 3;
    const int lrow = lane & 7;
    const int a_ro = (lsub & 1) * 8;
    const int a_ko = (lsub >> 1) * 16;
    const int b_ro = (lsub >> 1) * 8;
    const int b_ko = (lsub & 1) * 16;

    auto issueK = [&](int c, int buf) {
        const int kc0 = c * 64;
        const uint32_t bs = sbase + buf * FA_BUF;
#pragma unroll
        for (int i = 0; i < 2; i++) {
            const int f = tid + i * 256;
            const int row = f >> 3, seg = (f & 7) * 16;
            const uint32_t so = SWZ(row * 128 + seg);
            cp16(bs + FA_A + so, (const char*)(qp + (size_t)row * UU + kc0) + seg);
        }
#pragma unroll
        for (int i = 0; i < 10; i++) {
            const int f = tid + i * 256;
            const int row = f >> 3, seg = (f & 7) * 16;
            const int j = iclamp(kstart + row, 0, SS - 1);
            const uint32_t so = SWZ(row * 128 + seg);
            cp16(bs + FA_B + so, (const char*)(kp + (size_t)j * UU + kc0) + seg);
        }
        CP_COMMIT();
    };

    float acc[2][10][4];
#pragma unroll
    for (int mt = 0; mt < 2; mt++)
#pragma unroll
        for (int nt = 0; nt < 10; nt++)
#pragma unroll
            for (int i = 0; i < 4; i++) acc[mt][nt][i] = 0.f;

    issueK(0, 0);

    const int wm = (warp & 1) * 32;
    const int wng = warp >> 1;
    const int wn = wng * 80;

    for (int c = 0; c < 8; c++) {
        if (c < 7) { issueK(c + 1, (c + 1) & 1); CP_WAIT(1); }
        else       { CP_WAIT(0); }
        __syncthreads();

        const uint32_t bs = sbase + (c & 1) * FA_BUF;
#pragma unroll
        for (int ks = 0; ks < 4; ks++) {
            const int kb = ks * 32;
            uint32_t ah[2][4];
#pragma unroll
            for (int mt = 0; mt < 2; mt++) {
                const uint32_t off = SWZ((wm + mt * 16 + lrow + a_ro) * 128 + kb + a_ko);
                ldm_x4(ah[mt], bs + FA_A + off);
            }
#pragma unroll
            for (int ntp = 0; ntp < 5; ntp++) {
                const uint32_t off = SWZ((wn + ntp * 16 + b_ro + lrow) * 128 + kb + b_ko);
                uint32_t bh[4];
                ldm_x4(bh, bs + FA_B + off);
#pragma unroll
                for (int t = 0; t < 2; t++)
#pragma unroll
                    for (int mt = 0; mt < 2; mt++)
                        mma_f16(acc[mt][ntp * 2 + t], ah[mt], bh + t * 2);
            }
        }
        __syncthreads();
    }

    auto issueV = [&](int kc, int vbuf) {
        const uint32_t bs = sbase + V_OFF + vbuf * 65536;
#pragma unroll
        for (int i = 0; i < 16; i++) {
            const int f = tid + i * 256;
            const int sub = f >> 9;
            const int row = (f >> 3) & 63;
            const int seg = (f & 7) * 16;
            const int j = iclamp(kstart + kc * 64 + row, 0, SS - 1);
            const uint32_t so = SWZ(row * 128 + seg);
            cp16(bs + sub * 8192 + so,
                 (const char*)(vp + (size_t)j * UU + sub * 64) + seg);
        }
        CP_COMMIT();
    };
    issueV(0, 0);

    // Register softmax (no max pass)
    const int grp = lane >> 2;
    const int qd  = lane & 3;
    const int chi = SS - 1 - kstart;

    float* redsum = (float*)(sm + RED_OFF);

    int cminA[2], cmaxA[2], cminB[2], cmaxB[2];
    int rowA[2], rowB[2];
#pragma unroll
    for (int mt = 0; mt < 2; mt++) {
        rowA[mt] = wm + mt * 16 + grp;
        rowB[mt] = rowA[mt] + 8;
        cminA[mt] = (rowA[mt] > -kstart) ? rowA[mt] : -kstart;
        cmaxA[mt] = (rowA[mt] + 256 < chi) ? rowA[mt] + 256 : chi;
        cminB[mt] = (rowB[mt] > -kstart) ? rowB[mt] : -kstart;
        cmaxB[mt] = (rowB[mt] + 256 < chi) ? rowB[mt] + 256 : chi;
    }

    float sA[2] = {0.f, 0.f}, sB[2] = {0.f, 0.f};
#pragma unroll
    for (int mt = 0; mt < 2; mt++) {
#pragma unroll
        for (int nt = 0; nt < 10; nt++) {
            const int c0 = wn + nt * 8 + qd * 2;
            const int c1 = c0 + 1;
            float e;
            e = (c0 >= cminA[mt] && c0 <= cmaxA[mt]) ? __expf(acc[mt][nt][0] * SCALE) : 0.f;
            acc[mt][nt][0] = e; sA[mt] += e;
            e = (c1 >= cminA[mt] && c1 <= cmaxA[mt]) ? __expf(acc[mt][nt][1] * SCALE) : 0.f;
            acc[mt][nt][1] = e; sA[mt] += e;
            e = (c0 >= cminB[mt] && c0 <= cmaxB[mt]) ? __expf(acc[mt][nt][2] * SCALE) : 0.f;
            acc[mt][nt][2] = e; sB[mt] += e;
            e = (c1 >= cminB[mt] && c1 <= cmaxB[mt]) ? __expf(acc[mt][nt][3] * SCALE) : 0.f;
            acc[mt][nt][3] = e; sB[mt] += e;
        }
    }
#pragma unroll
    for (int off = 1; off <= 2; off <<= 1) {
#pragma unroll
        for (int mt = 0; mt < 2; mt++) {
            sA[mt] += __shfl_xor_sync(0xFFFFFFFFu, sA[mt], off);
            sB[mt] += __shfl_xor_sync(0xFFFFFFFFu, sB[mt], off);
        }
    }
    if (qd == 0) {
#pragma unroll
        for (int mt = 0; mt < 2; mt++) {
            redsum[wng * 64 + rowA[mt]] = sA[mt];
            redsum[wng * 64 + rowB[mt]] = sB[mt];
        }
    }

    // store unnormalized P (fp16)
#pragma unroll
    for (int mt = 0; mt < 2; mt++) {
#pragma unroll
        for (int nt = 0; nt < 10; nt++) {
            const int c0 = wn + nt * 8 + qd * 2;
            const uint32_t base0 = P_OFF + (c0 >> 6) * 8192;
            const uint32_t oA = base0 + SWZ(rowA[mt] * 128 + (c0 & 63) * 2);
            const uint32_t oB = base0 + SWZ(rowB[mt] * 128 + (c0 & 63) * 2);
            *(__half2*)(sm + oA) = __half2(__float2half_rn(acc[mt][nt][0]),
                                           __float2half_rn(acc[mt][nt][1]));
            *(__half2*)(sm + oB) = __half2(__float2half_rn(acc[mt][nt][2]),
                                           __float2half_rn(acc[mt][nt][3]));
        }
    }
    __syncthreads();

    float invA[2], invB[2];
#pragma unroll
    for (int mt = 0; mt < 2; mt++) {
        invA[mt] = 1.0f / (redsum[rowA[mt]] + redsum[64 + rowA[mt]]
                         + redsum[128 + rowA[mt]] + redsum[192 + rowA[mt]]);
        invB[mt] = 1.0f / (redsum[rowB[mt]] + redsum[64 + rowB[mt]]
                         + redsum[128 + rowB[mt]] + redsum[192 + rowB[mt]]);
    }

    // Phase 2: out = P V (kc outer, full 512 d)
    const int wd = wng * 128;
    const int sb = wd >> 6;

    float acc2[2][16][4];
#pragma unroll
    for (int mt = 0; mt < 2; mt++)
#pragma unroll
        for (int nt = 0; nt < 16; nt++)
#pragma unroll
            for (int i = 0; i < 4; i++) acc2[mt][nt][i] = 0.f;

    for (int kc = 0; kc < 5; kc++) {
        if (kc < 4) { issueV(kc + 1, (kc + 1) & 1); CP_WAIT(1); }
        else        { CP_WAIT(0); }
        __syncthreads();

        const uint32_t Vb = sbase + V_OFF + (kc & 1) * 65536;
        const uint32_t Ph = sbase + P_OFF + kc * 8192;

#pragma unroll
        for (int ks = 0; ks < 4; ks++) {
            uint32_t ah[2][4];
#pragma unroll
            for (int mt = 0; mt < 2; mt++) {
                const uint32_t off = SWZ((wm + mt * 16 + lrow + a_ro) * 128 + ks * 32 + a_ko);
                ldm_x4(ah[mt], Ph + off);
            }
#pragma unroll
            for (int sub2 = 0; sub2 < 2; sub2++) {
                const uint32_t Vt = Vb + (sb + sub2) * 8192;
#pragma unroll
                for (int ntp = 0; ntp < 4; ntp++) {
                    const uint32_t off = SWZ((ks * 16 + (lsub & 1) * 8 + lrow) * 128
                                             + (ntp * 16 + (lsub >> 1) * 8) * 2);
                    uint32_t bh[4];
                    ldm_x4t(bh, Vt + off);
#pragma unroll
                    for (int t = 0; t < 2; t++)
#pragma unroll
                        for (int mt = 0; mt < 2; mt++)
                            mma_f16(acc2[mt][sub2 * 8 + ntp * 2 + t], ah[mt], bh + t * 2);
                }
            }
        }
        __syncthreads();
    }

#pragma unroll
    for (int mt = 0; mt < 2; mt++) {
        const int r0 = q0 + wm + mt * 16 + grp;
#pragma unroll
        for (int sub2 = 0; sub2 < 2; sub2++) {
#pragma unroll
            for (int ntp = 0; ntp < 4; ntp++) {
#pragma unroll
                for (int t = 0; t < 2; t++) {
                    const int col = wd + sub2 * 64 + ntp * 16 + t * 8 + qd * 2;
                    const int idx = sub2 * 8 + ntp * 2 + t;
                    *(float2*)&out[((size_t)b * SS + r0) * UU + col] =
                        make_float2(acc2[mt][idx][0] * invA[mt], acc2[mt][idx][1] * invA[mt]);
                    *(float2*)&out[((size_t)b * SS + r0 + 8) * UU + col] =
                        make_float2(acc2[mt][idx][2] * invB[mt], acc2[mt][idx][3] * invB[mt]);
                }
            }
        }
    }
}

// ---------------------------------------------------------------------------
extern "C" void kernel_launch(void* const* d_in, const int* in_sizes, int n_in,
                              void* d_out, int out_size)
{
    const float* x  = (const float*)d_in[0];
    const float* Wq = (const float*)d_in[1];
    const float* Wk = (const float*)d_in[2];
    const float* Wv = (const float*)d_in[3];
    const float* bq = (const float*)d_in[4];
    const float* bk = (const float*)d_in[5];
    const float* bv = (const float*)d_in[6];
    float* out = (float*)d_out;

    cudaFuncSetAttribute(qkv_tc,
                         cudaFuncAttributeMaxDynamicSharedMemorySize, GEMM_SMEM);
    cudaFuncSetAttribute(attn_fused,
                         cudaFuncAttributeMaxDynamicSharedMemorySize, FA_SMEM);

    // Single merged prep launch: 8192 x-blocks + 768 W-blocks
    prep_all<<<8960, 256>>>(x, Wq, Wk, Wv);
    qkv_tc<<<dim3(UU / 128, BB * SS / 128, 3), 256, GEMM_SMEM>>>(bq, bk, bv);
    attn_fused<<<dim3(NT2, BB), 256, FA_SMEM>>>(out);
}